// round 5
// baseline (speedup 1.0000x reference)
#include <cuda_runtime.h>
#include <cuda_bf16.h>

#define NIMG 64
#define HW   (224 * 224)          // 50176, divisible by 4
#define NPIX (NIMG * HW)          // 3,211,264
#define RXD  64
#define RYD  32
#define RZD  32
#define LUT_PER_IMG (RXD * RYD * RZD * 3)   // 196608 floats

__device__ __forceinline__ float clamp01(float v) { return __saturatef(v); }

// sRGB -> linear (select semantics identical to reference's mask blend)
__device__ __forceinline__ float srgb2lin(float c) {
    float hi = __powf((c + 0.055f) * (1.0f / 1.055f), 2.4f);
    return (c < 0.04045f) ? (c * (1.0f / 12.92f)) : hi;
}

// linear -> sRGB
__device__ __forceinline__ float lin2srgb(float c) {
    float cl = fmaxf(c, 1e-10f);
    float hi = 1.055f * __powf(cl, (1.0f / 2.4f)) - 0.055f;
    return (c < 0.0031308f) ? (12.92f * c) : hi;
}

__device__ __forceinline__ void process_pixel(
    float r, float g, float b,
    const float* __restrict__ lut,
    float& ro, float& go, float& bo)
{
    // ---- RGB -> XYZ ----
    float rl = srgb2lin(r), gl = srgb2lin(g), bl = srgb2lin(b);
    float x = 0.4124f * rl + 0.3576f * gl + 0.1805f * bl;
    float y = 0.2126f * rl + 0.7152f * gl + 0.0722f * bl;
    float z = 0.0193f * rl + 0.1192f * gl + 0.9504f * bl;

    // ---- XYZ -> LUV ----
    float denom = x + 15.0f * y + 3.0f * z + 1e-10f;
    float rd = __fdividef(1.0f, denom);
    float up = 4.0f * x * rd;
    float vp = 9.0f * y * rd;
    // (6/29)^3 = 0.0088564517 ; (29/3)^3 = 903.2962963
    float ycl = fmaxf(y, 1e-10f);
    float Lbig = 116.0f * __powf(ycl, (1.0f / 3.0f)) - 16.0f;
    float L = (y < 0.0088564517f) ? (903.2962963f * y) : Lbig;
    float u = 13.0f * L * (up - 0.1978f);
    float v = 13.0f * L * (vp - 0.4683f);
    float cx = L * 0.01f;               // L/100
    float cy = (u + 100.0f) * 0.005f;   // (u+100)/200
    float cz = (v + 100.0f) * 0.005f;

    // ---- trilinear LUT (per-corner clamped indices, fp = s - floor(s)) ----
    float sx = cx * (float)(RXD - 1);
    float sy = cy * (float)(RYD - 1);
    float sz = cz * (float)(RZD - 1);
    float fx = floorf(sx), fy = floorf(sy), fz = floorf(sz);
    float px = sx - fx, py = sy - fy, pz = sz - fz;
    int ixf = (int)fx, iyf = (int)fy, izf = (int)fz;
    int ix0 = min(max(ixf,     0), RXD - 1);
    int ix1 = min(max(ixf + 1, 0), RXD - 1);
    int iy0 = min(max(iyf,     0), RYD - 1);
    int iy1 = min(max(iyf + 1, 0), RYD - 1);
    int iz0 = min(max(izf,     0), RZD - 1);
    int iz1 = min(max(izf + 1, 0), RZD - 1);

    int ax0 = ix0 * (RYD * RZD * 3), ax1 = ix1 * (RYD * RZD * 3);
    int ay0 = iy0 * (RZD * 3),       ay1 = iy1 * (RZD * 3);
    int az0 = iz0 * 3,               az1 = iz1 * 3;

    // Gather all 24 corner values up-front (8 corners x 3 channels) so ptxas
    // can front-batch the LDGs (high MLP -> latency hiding), then combine.
    const float* p000 = lut + (ax0 + ay0 + az0);
    const float* p001 = lut + (ax0 + ay0 + az1);
    const float* p010 = lut + (ax0 + ay1 + az0);
    const float* p011 = lut + (ax0 + ay1 + az1);
    const float* p100 = lut + (ax1 + ay0 + az0);
    const float* p101 = lut + (ax1 + ay0 + az1);
    const float* p110 = lut + (ax1 + ay1 + az0);
    const float* p111 = lut + (ax1 + ay1 + az1);

    float c000x = __ldg(p000 + 0), c000y = __ldg(p000 + 1), c000z = __ldg(p000 + 2);
    float c001x = __ldg(p001 + 0), c001y = __ldg(p001 + 1), c001z = __ldg(p001 + 2);
    float c010x = __ldg(p010 + 0), c010y = __ldg(p010 + 1), c010z = __ldg(p010 + 2);
    float c011x = __ldg(p011 + 0), c011y = __ldg(p011 + 1), c011z = __ldg(p011 + 2);
    float c100x = __ldg(p100 + 0), c100y = __ldg(p100 + 1), c100z = __ldg(p100 + 2);
    float c101x = __ldg(p101 + 0), c101y = __ldg(p101 + 1), c101z = __ldg(p101 + 2);
    float c110x = __ldg(p110 + 0), c110y = __ldg(p110 + 1), c110z = __ldg(p110 + 2);
    float c111x = __ldg(p111 + 0), c111y = __ldg(p111 + 1), c111z = __ldg(p111 + 2);

    float wx0 = 1.0f - px, wx1 = px;
    float wy0 = 1.0f - py, wy1 = py;
    float wz0 = 1.0f - pz, wz1 = pz;

    float w000 = wx0 * wy0 * wz0, w001 = wx0 * wy0 * wz1;
    float w010 = wx0 * wy1 * wz0, w011 = wx0 * wy1 * wz1;
    float w100 = wx1 * wy0 * wz0, w101 = wx1 * wy0 * wz1;
    float w110 = wx1 * wy1 * wz0, w111 = wx1 * wy1 * wz1;

    float a0 = w000 * c000x + w001 * c001x + w010 * c010x + w011 * c011x
             + w100 * c100x + w101 * c101x + w110 * c110x + w111 * c111x;
    float a1 = w000 * c000y + w001 * c001y + w010 * c010y + w011 * c011y
             + w100 * c100y + w101 * c101y + w110 * c110y + w111 * c111y;
    float a2 = w000 * c000z + w001 * c001z + w010 * c010z + w011 * c011z
             + w100 * c100z + w101 * c101z + w110 * c110z + w111 * c111z;

    a0 = clamp01(a0);
    a1 = clamp01(a1);
    a2 = clamp01(a2);

    // ---- LUV -> XYZ ----
    float L2 = a0 * 100.0f;
    float u2 = a1 * 200.0f - 100.0f;
    float v2 = a2 * 200.0f - 100.0f;
    float ti = __fdividef(1.0f, 13.0f * L2 + 1e-10f);
    float up2 = u2 * ti + 0.1978f;
    float vp2 = v2 * ti + 0.4683f;
    // (3/29)^3 = 0.00110705646
    float q = (L2 + 16.0f) * (1.0f / 116.0f);
    float ybig = q * q * q;
    float y2 = (L2 <= 8.0f) ? (L2 * 0.00110705646f) : ybig;
    float dd = __fdividef(1.0f, 4.0f * vp2 + 1e-10f);
    float x2 = y2 * 9.0f * up2 * dd;
    float z2 = y2 * (12.0f - 3.0f * up2 - 20.0f * vp2) * dd;
    x2  = fminf(fmaxf(x2, 0.0f), 1.1f);
    float y2c = fminf(fmaxf(y2, 0.0f), 1.1f);
    z2  = fminf(fmaxf(z2, 0.0f), 1.1f);

    // ---- XYZ -> RGB ----
    float rr =  3.2406f * x2 - 1.5372f * y2c - 0.4986f * z2;
    float gg = -0.9689f * x2 + 1.8758f * y2c + 0.0415f * z2;
    float bb =  0.0557f * x2 - 0.2040f * y2c + 1.0570f * z2;

    ro = clamp01(lin2srgb(rr));
    go = clamp01(lin2srgb(gg));
    bo = clamp01(lin2srgb(bb));
}

__global__ __launch_bounds__(256)
void ColorTransformsCIELUV_kernel(
    const float* __restrict__ imgs,
    const float* __restrict__ params,
    float* __restrict__ out)
{
    int t = blockIdx.x * blockDim.x + threadIdx.x;
    int pix0 = t << 2;
    if (pix0 >= NPIX) return;
    int n  = pix0 / HW;             // quad never crosses image boundary (HW % 4 == 0)
    int hw = pix0 - n * HW;

    const float* base = imgs + (size_t)n * (3 * HW) + hw;
    float4 R = *reinterpret_cast<const float4*>(base);
    float4 G = *reinterpret_cast<const float4*>(base + HW);
    float4 B = *reinterpret_cast<const float4*>(base + 2 * HW);

    const float* __restrict__ lut = params + (size_t)n * LUT_PER_IMG;

    float rin[4] = {R.x, R.y, R.z, R.w};
    float gin[4] = {G.x, G.y, G.z, G.w};
    float bin[4] = {B.x, B.y, B.z, B.w};
    float rou[4], gou[4], bou[4];

#pragma unroll
    for (int k = 0; k < 4; k++) {
        process_pixel(rin[k], gin[k], bin[k], lut, rou[k], gou[k], bou[k]);
    }

    float* obase = out + (size_t)n * (3 * HW) + hw;
    *reinterpret_cast<float4*>(obase)          = make_float4(rou[0], rou[1], rou[2], rou[3]);
    *reinterpret_cast<float4*>(obase + HW)     = make_float4(gou[0], gou[1], gou[2], gou[3]);
    *reinterpret_cast<float4*>(obase + 2 * HW) = make_float4(bou[0], bou[1], bou[2], bou[3]);
}

extern "C" void kernel_launch(void* const* d_in, const int* in_sizes, int n_in,
                              void* d_out, int out_size) {
    const float* imgs   = (const float*)d_in[0];
    const float* params = (const float*)d_in[1];
    float* out = (float*)d_out;

    int nthreads = NPIX / 4;                    // 802,816
    int block = 256;
    int grid = (nthreads + block - 1) / block;  // 3136
    ColorTransformsCIELUV_kernel<<<grid, block>>>(imgs, params, out);
}

// round 6
// speedup vs baseline: 1.0643x; 1.0643x over previous
#include <cuda_runtime.h>
#include <cuda_bf16.h>

#define NIMG 64
#define HW   (224 * 224)          // 50176, divisible by 4
#define NPIX (NIMG * HW)          // 3,211,264
#define RXD  64
#define RYD  32
#define RZD  32
#define ENTRIES_PER_IMG (RXD * RYD * RZD)        // 65536
#define LUT_PER_IMG (ENTRIES_PER_IMG * 3)        // 196608 floats
#define TOTAL_ENTRIES (NIMG * ENTRIES_PER_IMG)   // 4,194,304

// 64 MB padded-float4 LUT scratch (sanctioned __device__ global scratch).
__device__ float4 g_lut4[TOTAL_ENTRIES];

// ---------------- Prologue: repack AoS-12B LUT -> padded float4 ----------------
// Each thread consumes 12 source floats (3 aligned float4 loads) = 4 entries,
// writes 4 float4. Fully coalesced on both sides. 1,048,576 threads total.
__global__ __launch_bounds__(256)
void repack_lut_kernel(const float* __restrict__ params)
{
    int t = blockIdx.x * blockDim.x + threadIdx.x;   // < TOTAL_ENTRIES/4
    const float4* src = reinterpret_cast<const float4*>(params) + 3 * (size_t)t;
    float4 a = __ldg(src + 0);
    float4 b = __ldg(src + 1);
    float4 c = __ldg(src + 2);
    float4* dst = g_lut4 + 4 * (size_t)t;
    dst[0] = make_float4(a.x, a.y, a.z, 0.0f);
    dst[1] = make_float4(a.w, b.x, b.y, 0.0f);
    dst[2] = make_float4(b.z, b.w, c.x, 0.0f);
    dst[3] = make_float4(c.y, c.z, c.w, 0.0f);
}

// ---------------- Main fused kernel ----------------

__device__ __forceinline__ float clamp01(float v) { return __saturatef(v); }

__device__ __forceinline__ float srgb2lin(float c) {
    float hi = __powf((c + 0.055f) * (1.0f / 1.055f), 2.4f);
    return (c < 0.04045f) ? (c * (1.0f / 12.92f)) : hi;
}

__device__ __forceinline__ float lin2srgb(float c) {
    float cl = fmaxf(c, 1e-10f);
    float hi = 1.055f * __powf(cl, (1.0f / 2.4f)) - 0.055f;
    return (c < 0.0031308f) ? (12.92f * c) : hi;
}

__device__ __forceinline__ void process_pixel(
    float r, float g, float b,
    const float4* __restrict__ lut4,
    float& ro, float& go, float& bo)
{
    // ---- RGB -> XYZ ----
    float rl = srgb2lin(r), gl = srgb2lin(g), bl = srgb2lin(b);
    float x = 0.4124f * rl + 0.3576f * gl + 0.1805f * bl;
    float y = 0.2126f * rl + 0.7152f * gl + 0.0722f * bl;
    float z = 0.0193f * rl + 0.1192f * gl + 0.9504f * bl;

    // ---- XYZ -> LUV ----
    float denom = x + 15.0f * y + 3.0f * z + 1e-10f;
    float rd = __fdividef(1.0f, denom);
    float up = 4.0f * x * rd;
    float vp = 9.0f * y * rd;
    float ycl = fmaxf(y, 1e-10f);
    float Lbig = 116.0f * __powf(ycl, (1.0f / 3.0f)) - 16.0f;
    float L = (y < 0.0088564517f) ? (903.2962963f * y) : Lbig;   // (6/29)^3, (29/3)^3
    float u = 13.0f * L * (up - 0.1978f);
    float v = 13.0f * L * (vp - 0.4683f);
    float cx = L * 0.01f;
    float cy = (u + 100.0f) * 0.005f;
    float cz = (v + 100.0f) * 0.005f;

    // ---- trilinear LUT (per-corner clamped indices, fp = s - floor(s)) ----
    float sx = cx * (float)(RXD - 1);
    float sy = cy * (float)(RYD - 1);
    float sz = cz * (float)(RZD - 1);
    float fx = floorf(sx), fy = floorf(sy), fz = floorf(sz);
    float px = sx - fx, py = sy - fy, pz = sz - fz;
    int ixf = (int)fx, iyf = (int)fy, izf = (int)fz;
    int ix0 = min(max(ixf,     0), RXD - 1);
    int ix1 = min(max(ixf + 1, 0), RXD - 1);
    int iy0 = min(max(iyf,     0), RYD - 1);
    int iy1 = min(max(iyf + 1, 0), RYD - 1);
    int iz0 = min(max(izf,     0), RZD - 1);
    int iz1 = min(max(izf + 1, 0), RZD - 1);

    int ex0 = ix0 * (RYD * RZD), ex1 = ix1 * (RYD * RZD);
    int ey0 = iy0 * RZD,         ey1 = iy1 * RZD;

    // 8 corner gathers as single LDG.128 each (was 24 scalar LDGs).
    float4 C000 = __ldg(lut4 + (ex0 + ey0 + iz0));
    float4 C001 = __ldg(lut4 + (ex0 + ey0 + iz1));
    float4 C010 = __ldg(lut4 + (ex0 + ey1 + iz0));
    float4 C011 = __ldg(lut4 + (ex0 + ey1 + iz1));
    float4 C100 = __ldg(lut4 + (ex1 + ey0 + iz0));
    float4 C101 = __ldg(lut4 + (ex1 + ey0 + iz1));
    float4 C110 = __ldg(lut4 + (ex1 + ey1 + iz0));
    float4 C111 = __ldg(lut4 + (ex1 + ey1 + iz1));

    float wx0 = 1.0f - px, wx1 = px;
    float wy0 = 1.0f - py, wy1 = py;
    float wz0 = 1.0f - pz, wz1 = pz;

    float w000 = wx0 * wy0 * wz0, w001 = wx0 * wy0 * wz1;
    float w010 = wx0 * wy1 * wz0, w011 = wx0 * wy1 * wz1;
    float w100 = wx1 * wy0 * wz0, w101 = wx1 * wy0 * wz1;
    float w110 = wx1 * wy1 * wz0, w111 = wx1 * wy1 * wz1;

    float a0 = w000 * C000.x + w001 * C001.x + w010 * C010.x + w011 * C011.x
             + w100 * C100.x + w101 * C101.x + w110 * C110.x + w111 * C111.x;
    float a1 = w000 * C000.y + w001 * C001.y + w010 * C010.y + w011 * C011.y
             + w100 * C100.y + w101 * C101.y + w110 * C110.y + w111 * C111.y;
    float a2 = w000 * C000.z + w001 * C001.z + w010 * C010.z + w011 * C011.z
             + w100 * C100.z + w101 * C101.z + w110 * C110.z + w111 * C111.z;

    a0 = clamp01(a0);
    a1 = clamp01(a1);
    a2 = clamp01(a2);

    // ---- LUV -> XYZ ----
    float L2 = a0 * 100.0f;
    float u2 = a1 * 200.0f - 100.0f;
    float v2 = a2 * 200.0f - 100.0f;
    float ti = __fdividef(1.0f, 13.0f * L2 + 1e-10f);
    float up2 = u2 * ti + 0.1978f;
    float vp2 = v2 * ti + 0.4683f;
    float q = (L2 + 16.0f) * (1.0f / 116.0f);
    float ybig = q * q * q;
    float y2 = (L2 <= 8.0f) ? (L2 * 0.00110705646f) : ybig;    // (3/29)^3
    float dd = __fdividef(1.0f, 4.0f * vp2 + 1e-10f);
    float x2 = y2 * 9.0f * up2 * dd;
    float z2 = y2 * (12.0f - 3.0f * up2 - 20.0f * vp2) * dd;
    x2  = fminf(fmaxf(x2, 0.0f), 1.1f);
    float y2c = fminf(fmaxf(y2, 0.0f), 1.1f);
    z2  = fminf(fmaxf(z2, 0.0f), 1.1f);

    // ---- XYZ -> RGB ----
    float rr =  3.2406f * x2 - 1.5372f * y2c - 0.4986f * z2;
    float gg = -0.9689f * x2 + 1.8758f * y2c + 0.0415f * z2;
    float bb =  0.0557f * x2 - 0.2040f * y2c + 1.0570f * z2;

    ro = clamp01(lin2srgb(rr));
    go = clamp01(lin2srgb(gg));
    bo = clamp01(lin2srgb(bb));
}

__global__ __launch_bounds__(256)
void ColorTransformsCIELUV_kernel(
    const float* __restrict__ imgs,
    float* __restrict__ out)
{
    int t = blockIdx.x * blockDim.x + threadIdx.x;
    int pix0 = t << 2;
    if (pix0 >= NPIX) return;
    int n  = pix0 / HW;             // quad never crosses image boundary (HW % 4 == 0)
    int hw = pix0 - n * HW;

    const float* base = imgs + (size_t)n * (3 * HW) + hw;
    float4 R = *reinterpret_cast<const float4*>(base);
    float4 G = *reinterpret_cast<const float4*>(base + HW);
    float4 B = *reinterpret_cast<const float4*>(base + 2 * HW);

    const float4* __restrict__ lut4 = g_lut4 + (size_t)n * ENTRIES_PER_IMG;

    float rin[4] = {R.x, R.y, R.z, R.w};
    float gin[4] = {G.x, G.y, G.z, G.w};
    float bin[4] = {B.x, B.y, B.z, B.w};
    float rou[4], gou[4], bou[4];

#pragma unroll
    for (int k = 0; k < 4; k++) {
        process_pixel(rin[k], gin[k], bin[k], lut4, rou[k], gou[k], bou[k]);
    }

    float* obase = out + (size_t)n * (3 * HW) + hw;
    *reinterpret_cast<float4*>(obase)          = make_float4(rou[0], rou[1], rou[2], rou[3]);
    *reinterpret_cast<float4*>(obase + HW)     = make_float4(gou[0], gou[1], gou[2], gou[3]);
    *reinterpret_cast<float4*>(obase + 2 * HW) = make_float4(bou[0], bou[1], bou[2], bou[3]);
}

extern "C" void kernel_launch(void* const* d_in, const int* in_sizes, int n_in,
                              void* d_out, int out_size) {
    const float* imgs   = (const float*)d_in[0];
    const float* params = (const float*)d_in[1];
    float* out = (float*)d_out;

    // Prologue: repack LUT to padded float4 (65,536 entries/img, 16 B each).
    {
        int nthreads = TOTAL_ENTRIES / 4;            // 1,048,576
        repack_lut_kernel<<<nthreads / 256, 256>>>(params);
    }

    // Main fused kernel.
    {
        int nthreads = NPIX / 4;                     // 802,816
        int grid = (nthreads + 255) / 256;           // 3136
        ColorTransformsCIELUV_kernel<<<grid, 256>>>(imgs, out);
    }
}